// round 1
// baseline (speedup 1.0000x reference)
#include <cuda_runtime.h>

#define PLANES 96      // B*C = 32*3
#define BINS   25
#define H      512
#define W      512
#define HW     262144.0f

// Scratch histograms: [tensor(x=0,y=1)][plane][bin], integer-exact counts.
__device__ unsigned int g_hist[2][PLANES][BINS];

__global__ void zero_hist_kernel() {
    int i = blockIdx.x * blockDim.x + threadIdx.x;
    if (i < 2 * PLANES * BINS) ((unsigned int*)g_hist)[i] = 0u;
}

// One block = one 32x32 output tile of one (tensor, plane).
// grid = (8, 8, 192); blockDim = 256.
__global__ __launch_bounds__(256) void blur_hist_kernel(
    const float* __restrict__ x, const float* __restrict__ y) {

    __shared__ float        s_in[69][72];   // 69x69 halo, pad to 72 for coalesced/bank-friendly rows
    __shared__ float        s_tmp[69][33];  // horizontally filtered, stride-2 (32 cols + pad)
    __shared__ unsigned int s_hist[BINS];

    const int tid   = threadIdx.x;
    const int pz    = blockIdx.z;            // 0..191
    const int tsel  = (pz >= PLANES) ? 1 : 0;
    const int plane = pz - tsel * PLANES;
    const float* __restrict__ in = (tsel ? y : x) + (size_t)plane * H * W;

    if (tid < BINS) s_hist[tid] = 0u;

    // Input halo origin: output rows [ty*32, ty*32+31] need input rows [ty*64-3, ty*64+65] (69 rows).
    const int r0 = (int)blockIdx.y * 64 - 3;
    const int c0 = (int)blockIdx.x * 64 - 3;

    for (int i = tid; i < 69 * 69; i += 256) {
        int r = i / 69;
        int c = i - r * 69;
        int gr = r0 + r, gc = c0 + c;
        float v = 0.0f;
        if ((unsigned)gr < (unsigned)H && (unsigned)gc < (unsigned)W)
            v = in[gr * W + gc];
        s_in[r][c] = v;
    }
    __syncthreads();

    // Pascal row [1,6,15,20,15,6,1]/64 — all weights exact dyadic fp32.
    const float w0 = 0.015625f, w1 = 0.09375f, w2 = 0.234375f, w3 = 0.3125f;

    // Horizontal pass, stride 2: 69 rows x 32 output cols.
    for (int i = tid; i < 69 * 32; i += 256) {
        int r  = i >> 5;
        int oc = i & 31;
        const float* p = &s_in[r][2 * oc];
        s_tmp[r][oc] = w0 * (p[0] + p[6]) + w1 * (p[1] + p[5])
                     + w2 * (p[2] + p[4]) + w3 * p[3];
    }
    __syncthreads();

    // Vertical pass, stride 2, then bin. 32x32 outputs.
    for (int i = tid; i < 32 * 32; i += 256) {
        int oy = i >> 5;
        int ox = i & 31;
        int rb = 2 * oy;
        float v = w0 * (s_tmp[rb][ox]     + s_tmp[rb + 6][ox])
                + w1 * (s_tmp[rb + 1][ox] + s_tmp[rb + 5][ox])
                + w2 * (s_tmp[rb + 2][ox] + s_tmp[rb + 4][ox])
                + w3 *  s_tmp[rb + 3][ox];
        // torch.histc semantics: values outside [0,1] ignored; floor(v*bins) clipped to [0,24].
        if (v >= 0.0f && v <= 1.0f) {
            int b = (int)floorf(v * 25.0f);
            b = b < 0 ? 0 : (b > 24 ? 24 : b);
            atomicAdd(&s_hist[b], 1u);
        }
    }
    __syncthreads();

    if (tid < BINS)
        atomicAdd(&g_hist[tsel][plane][tid], s_hist[tid]);
}

// Cosine similarity per plane + mean. One block, 128 threads (96 active).
__global__ void finalize_kernel(float* __restrict__ out) {
    __shared__ float s[128];
    const int t = threadIdx.x;
    float cosv = 0.0f;
    if (t < PLANES) {
        float dot = 0.0f, nx = 0.0f, ny = 0.0f;
#pragma unroll
        for (int b = 0; b < BINS; b++) {
            float xv = (float)g_hist[0][t][b];
            float yv = (float)g_hist[1][t][b];
            dot = fmaf(xv, yv, dot);
            nx  = fmaf(xv, xv, nx);
            ny  = fmaf(yv, yv, ny);
        }
        // Reproduce reference scaling (hist/hw) + eps floor exactly.
        float nxs = fmaxf(sqrtf(nx) * (1.0f / HW), 1e-6f);
        float nys = fmaxf(sqrtf(ny) * (1.0f / HW), 1e-6f);
        cosv = (dot * (1.0f / (HW * HW))) / (nxs * nys);
    }
    s[t] = cosv;
    __syncthreads();
#pragma unroll
    for (int stride = 64; stride > 0; stride >>= 1) {
        if (t < stride) s[t] += s[t + stride];
        __syncthreads();
    }
    if (t == 0) out[0] = s[0] * (1.0f / 96.0f);
}

extern "C" void kernel_launch(void* const* d_in, const int* in_sizes, int n_in,
                              void* d_out, int out_size) {
    const float* x = (const float*)d_in[0];
    const float* y = (const float*)d_in[1];

    zero_hist_kernel<<<(2 * PLANES * BINS + 255) / 256, 256>>>();

    dim3 grid(8, 8, 2 * PLANES);   // (tiles_x, tiles_y, tensor*plane)
    blur_hist_kernel<<<grid, 256>>>(x, y);

    finalize_kernel<<<1, 128>>>((float*)d_out);
}

// round 2
// speedup vs baseline: 1.5820x; 1.5820x over previous
#include <cuda_runtime.h>

#define PLANES 96      // B*C
#define BINS   25
#define HH     512
#define WW     512
#define HWF    262144.0f
#define NBLK   1536    // 192 planes * 4 strips * 2 halves
#define FULLM  0xFFFFFFFFu

// Persistent scratch (zero-initialized at module load; the kernel restores the
// all-zero invariant at the end of every call -> deterministic, graph-safe).
__device__ unsigned int g_hist[2][PLANES][BINS];
__device__ unsigned int g_ticket;

// Horizontal 7-tap pascal filter at stride 2 for one input row, register/shuffle
// only. Lane l owns input cols [C+4l, C+4l+3] (one float4) and produces the two
// horizontally-filtered values for output cols strip*64 + 2l and +1.
__device__ __forceinline__ void conv_row(
    const float* __restrict__ rowp, bool rvalid, int lane,
    bool has_l, bool has_r, float& h0, float& h1)
{
    float4 v = {0.f, 0.f, 0.f, 0.f};
    float lh_y = 0.f, lh_z = 0.f, lh_w = 0.f, rh_x = 0.f, rh_y = 0.f;
    if (rvalid) {
        v = *(const float4*)(rowp + 4 * lane);
        if (lane == 0 && has_l) {                 // left halo: cols C-4..C-1
            float4 lh = *(const float4*)(rowp - 4);
            lh_y = lh.y; lh_z = lh.z; lh_w = lh.w;
        }
        if (lane == 31 && has_r) {                // right halo: cols C+128,C+129
            float2 rh = *(const float2*)(rowp + 128);
            rh_x = rh.x; rh_y = rh.y;
        }
    }
    float m1 = __shfl_up_sync(FULLM, v.w, 1);     // col C+4l-1
    float m2 = __shfl_up_sync(FULLM, v.z, 1);     // col C+4l-2
    float m3 = __shfl_up_sync(FULLM, v.y, 1);     // col C+4l-3
    float p4 = __shfl_down_sync(FULLM, v.x, 1);   // col C+4l+4
    float p5 = __shfl_down_sync(FULLM, v.y, 1);   // col C+4l+5
    if (lane == 0)  { m3 = lh_y; m2 = lh_z; m1 = lh_w; }
    if (lane == 31) { p4 = rh_x; p5 = rh_y; }

    const float w0 = 0.015625f, w1 = 0.09375f, w2 = 0.234375f, w3 = 0.3125f;
    // Same association as the round-1 kernel (rel_err was 0.0).
    h0 = w0 * (m3 + v.w) + w1 * (m2 + v.z) + w2 * (m1 + v.y) + w3 * v.x;
    h1 = w0 * (m1 + p5)  + w1 * (v.x + p4) + w2 * (v.y + v.w) + w3 * v.z;
}

__global__ __launch_bounds__(128) void fused_hist_loss_kernel(
    const float* __restrict__ x, const float* __restrict__ y,
    float* __restrict__ out)
{
    // Per-thread private bin counters: addr = bin*128 + tid -> every lane a
    // distinct bank, NO atomics, conflict-free regardless of bin distribution.
    __shared__ unsigned int s_cnt[BINS][128];
    __shared__ float        s_red[128];
    __shared__ unsigned int s_last;

    const int tid  = threadIdx.x;
    const int lane = tid & 31;
    const int wrp  = tid >> 5;           // 0..3

    const int bi    = blockIdx.x;
    const int half  = bi & 1;            // which 128-output-row half
    const int strip = (bi >> 1) & 3;     // 64-output-col strip
    const int pz    = bi >> 3;           // 0..191 (tensor*plane)
    const int tsel  = (pz >= PLANES) ? 1 : 0;
    const int plane = pz - tsel * PLANES;

    const float* __restrict__ in = (tsel ? y : x) + (size_t)plane * HH * WW;
    const int  C     = strip * 128;      // input col base
    const bool has_l = (strip > 0);
    const bool has_r = (strip < 3);
    const float* colbase = in + C;

    unsigned int* myc = &s_cnt[0][tid];  // + bin*128

#pragma unroll
    for (int i = tid; i < BINS * 128; i += 128) ((unsigned int*)s_cnt)[i] = 0;
    __syncthreads();

    // This warp's band: 32 output rows, input rows [64*band-3, 64*band+65].
    const int band = half * 4 + wrp;     // 0..7
    int r = 64 * band - 3;

    const float w0 = 0.015625f, w1 = 0.09375f, w2 = 0.234375f, w3 = 0.3125f;
    float a0,a1,a2,a3,a4,a5,a6, b0,b1,b2,b3,b4,b5,b6;

#define ROW(hA,hB) conv_row(colbase + (size_t)r * WW, (unsigned)r < (unsigned)HH, lane, has_l, has_r, hA, hB); r++
    ROW(a0, b0); ROW(a1, b1); ROW(a2, b2); ROW(a3, b3); ROW(a4, b4);

#pragma unroll 4
    for (int oy = 0; oy < 32; oy++) {
        ROW(a5, b5);
        ROW(a6, b6);
        float va = w0 * (a0 + a6) + w1 * (a1 + a5) + w2 * (a2 + a4) + w3 * a3;
        float vb = w0 * (b0 + b6) + w1 * (b1 + b5) + w2 * (b2 + b4) + w3 * b3;
        // torch.histc(v, 25, 0, 1) semantics
        if (va >= 0.0f && va <= 1.0f) {
            int bin = (int)(va * 25.0f); bin = bin > 24 ? 24 : bin;
            myc[bin * 128] += 1u;
        }
        if (vb >= 0.0f && vb <= 1.0f) {
            int bin = (int)(vb * 25.0f); bin = bin > 24 ? 24 : bin;
            myc[bin * 128] += 1u;
        }
        a0 = a2; a1 = a3; a2 = a4; a3 = a5; a4 = a6;
        b0 = b2; b1 = b3; b2 = b4; b3 = b5; b4 = b6;
    }
#undef ROW

    __syncthreads();

    // Block-reduce private counters -> 25 global atomics.
    for (int bin = wrp; bin < BINS; bin += 4) {
        unsigned int sum = 0;
#pragma unroll
        for (int j = 0; j < 4; j++) sum += s_cnt[bin][lane + 32 * j];
#pragma unroll
        for (int off = 16; off; off >>= 1) sum += __shfl_down_sync(FULLM, sum, off);
        if (lane == 0) atomicAdd(&g_hist[tsel][plane][bin], sum);
    }

    // Last-block finalize (threadFenceReduction pattern).
    __threadfence();
    __syncthreads();
    if (tid == 0) {
        unsigned int t = atomicAdd(&g_ticket, 1u);
        s_last = (t == NBLK - 1) ? 1u : 0u;
    }
    __syncthreads();
    if (!s_last) return;

    float cosv = 0.0f;
    if (tid < PLANES) {
        float dot = 0.0f, nx = 0.0f, ny = 0.0f;
#pragma unroll
        for (int b = 0; b < BINS; b++) {
            float xv = (float)__ldcg(&g_hist[0][tid][b]);
            float yv = (float)__ldcg(&g_hist[1][tid][b]);
            dot = fmaf(xv, yv, dot);
            nx  = fmaf(xv, xv, nx);
            ny  = fmaf(yv, yv, ny);
        }
        float nxs = fmaxf(sqrtf(nx) * (1.0f / HWF), 1e-6f);
        float nys = fmaxf(sqrtf(ny) * (1.0f / HWF), 1e-6f);
        cosv = (dot * (1.0f / (HWF * HWF))) / (nxs * nys);
    }
    s_red[tid] = cosv;
    __syncthreads();
#pragma unroll
    for (int stride = 64; stride > 0; stride >>= 1) {
        if (tid < stride) s_red[tid] += s_red[tid + stride];
        __syncthreads();
    }
    if (tid == 0) out[0] = s_red[0] * (1.0f / 96.0f);

    // Restore the all-zero scratch invariant for the next graph replay.
    __syncthreads();
    for (int i = tid; i < 2 * PLANES * BINS; i += 128)
        ((unsigned int*)g_hist)[i] = 0u;
    if (tid == 0) g_ticket = 0u;
}

extern "C" void kernel_launch(void* const* d_in, const int* in_sizes, int n_in,
                              void* d_out, int out_size) {
    const float* x = (const float*)d_in[0];
    const float* y = (const float*)d_in[1];
    fused_hist_loss_kernel<<<NBLK, 128>>>(x, y, (float*)d_out);
}

// round 3
// speedup vs baseline: 2.6863x; 1.6980x over previous
#include <cuda_runtime.h>

#define PLANES 96
#define BINS   25
#define HH     512
#define WW     512
#define HWF    262144.0f
#define NBLK   768
#define FULLM  0xFFFFFFFFu
#define W0 0.015625f
#define W1 0.09375f
#define W2 0.234375f
#define W3 0.3125f

__device__ unsigned int g_hist[2][PLANES][BINS];
__device__ unsigned int g_ticket;

struct Row { float4 q0, q1, q2, q3; };

// Lane owns input cols [8l-4, 8l+11] of its 256-col strip: 4 aligned float4s.
// No shuffles: all 7 taps for the 4 stride-2 outputs are lane-local.
__device__ __forceinline__ void load_row(Row& R, const float* __restrict__ base,
                                         int r, bool ok0, bool ok3) {
    float4 z = make_float4(0.f, 0.f, 0.f, 0.f);
    R.q0 = z; R.q1 = z; R.q2 = z; R.q3 = z;
    if ((unsigned)r < (unsigned)HH) {
        const float4* p = (const float4*)(base + (size_t)r * WW);
        if (ok0) R.q0 = p[0];
        R.q1 = p[1];
        R.q2 = p[2];
        if (ok3) R.q3 = p[3];
    }
}

// Horizontal 7-tap pascal, stride 2, 4 outputs per lane. Pairwise association
// identical to the round-1/2 kernels (rel_err was 0.0).
__device__ __forceinline__ void hconv(const Row& R, float h[4]) {
    h[0] = W0*(R.q0.y + R.q1.w) + W1*(R.q0.z + R.q1.z) + W2*(R.q0.w + R.q1.y) + W3*R.q1.x;
    h[1] = W0*(R.q0.w + R.q2.y) + W1*(R.q1.x + R.q2.x) + W2*(R.q1.y + R.q1.w) + W3*R.q1.z;
    h[2] = W0*(R.q1.y + R.q2.w) + W1*(R.q1.z + R.q2.z) + W2*(R.q1.w + R.q2.y) + W3*R.q2.x;
    h[3] = W0*(R.q1.w + R.q3.y) + W1*(R.q2.x + R.q3.x) + W2*(R.q2.y + R.q2.w) + W3*R.q2.z;
}

__global__ __launch_bounds__(128) void fused_hist_loss_kernel(
    const float* __restrict__ x, const float* __restrict__ y,
    float* __restrict__ out)
{
    __shared__ unsigned int s_cnt[BINS][128];  // per-thread counters, bank-conflict-free
    __shared__ float        s_red[128];
    __shared__ unsigned int s_last;

    const int tid  = threadIdx.x;
    const int lane = tid & 31;
    const int wrp  = tid >> 5;

    const int bi    = blockIdx.x;          // 768 = 192 planes * 2 strips * 2 block-bands
    const int strip = bi & 1;
    const int bb    = (bi >> 1) & 1;
    const int pz    = bi >> 2;             // 0..191
    const int tsel  = (pz >= PLANES) ? 1 : 0;
    const int plane = pz - tsel * PLANES;

    const float* __restrict__ in = (tsel ? y : x) + (size_t)plane * HH * WW;
    const float* base = in + strip * 256 + 8 * lane - 4;
    const bool ok0 = !(strip == 0 && lane == 0);    // left image edge
    const bool ok3 = !(strip == 1 && lane == 31);   // right image edge

    const int band = bb * 4 + wrp;          // 0..7: 32 output rows each
    const int rb0  = 64 * band - 3;
    unsigned int* myc = &s_cnt[0][tid];

    Row Ra, Rb;
    load_row(Ra, base, rb0, ok0, ok3);      // issue first loads before smem zero
    load_row(Rb, base, rb0 + 1, ok0, ok3);

#pragma unroll
    for (int i = tid; i < BINS * 128; i += 128) ((unsigned int*)s_cnt)[i] = 0u;
    __syncthreads();

    // Vertical conv via 3 rolling accumulators: input row ri feeds outputs
    // o in [ceil((ri-3)/2), floor((ri+3)/2)]; one output retires per 2 rows.
    float h[4], accA[4], accB[4], accC[4];

    hconv(Ra, h);                                           // row rb0   -> B w0
#pragma unroll
    for (int j = 0; j < 4; j++) { accA[j] = 0.f; accB[j] = W0 * h[j]; }
    load_row(Ra, base, rb0 + 2, ok0, ok3);
    hconv(Rb, h);                                           // row rb0+1 -> B w1
#pragma unroll
    for (int j = 0; j < 4; j++) accB[j] = fmaf(W1, h[j], accB[j]);
    load_row(Rb, base, rb0 + 3, ok0, ok3);
    hconv(Ra, h);                                           // row rb0+2 -> B w2, C w0
#pragma unroll
    for (int j = 0; j < 4; j++) { accB[j] = fmaf(W2, h[j], accB[j]); accC[j] = W0 * h[j]; }
    load_row(Ra, base, rb0 + 4, ok0, ok3);

#pragma unroll 1
    for (int g = 0; g < 33; g++) {
        hconv(Rb, h);                                       // even row rb0+3+2g
#pragma unroll
        for (int j = 0; j < 4; j++) {
            accA[j] = fmaf(W1, h[j], accA[j]);
            accB[j] = fmaf(W3, h[j], accB[j]);
            accC[j] = fmaf(W1, h[j], accC[j]);
        }
        load_row(Rb, base, g < 32 ? rb0 + 5 + 2 * g : -1, ok0, ok3);
        hconv(Ra, h);                                       // odd row rb0+4+2g
#pragma unroll
        for (int j = 0; j < 4; j++) accA[j] = fmaf(W0, h[j], accA[j]);
        if (g > 0) {                                        // accA = output row k0+g-1
#pragma unroll
            for (int j = 0; j < 4; j++) {
                float v = accA[j];
                // torch.histc(v, 25, 0, 1) semantics
                if (v >= 0.0f && v <= 1.0f) {
                    int b = (int)(v * 25.0f); b = b > 24 ? 24 : b;
                    myc[b * 128] += 1u;
                }
            }
        }
#pragma unroll
        for (int j = 0; j < 4; j++) {                       // retire + rotate
            accA[j] = fmaf(W2, h[j], accB[j]);
            accB[j] = fmaf(W2, h[j], accC[j]);
            accC[j] = W0 * h[j];
        }
        load_row(Ra, base, g < 32 ? rb0 + 6 + 2 * g : -1, ok0, ok3);
    }
    __syncthreads();

    // Block-reduce private counters -> 25 global atomics.
    for (int bin = wrp; bin < BINS; bin += 4) {
        unsigned int sum = 0;
#pragma unroll
        for (int j = 0; j < 4; j++) sum += s_cnt[bin][lane + 32 * j];
#pragma unroll
        for (int off = 16; off; off >>= 1) sum += __shfl_down_sync(FULLM, sum, off);
        if (lane == 0) atomicAdd(&g_hist[tsel][plane][bin], sum);
    }

    // Last-block finalize.
    __threadfence();
    __syncthreads();
    if (tid == 0) {
        unsigned int t = atomicAdd(&g_ticket, 1u);
        s_last = (t == NBLK - 1) ? 1u : 0u;
    }
    __syncthreads();
    if (!s_last) return;

    float cosv = 0.0f;
    if (tid < PLANES) {
        float dot = 0.0f, nx = 0.0f, ny = 0.0f;
#pragma unroll
        for (int b = 0; b < BINS; b++) {
            float xv = (float)__ldcg(&g_hist[0][tid][b]);
            float yv = (float)__ldcg(&g_hist[1][tid][b]);
            dot = fmaf(xv, yv, dot);
            nx  = fmaf(xv, xv, nx);
            ny  = fmaf(yv, yv, ny);
        }
        float nxs = fmaxf(sqrtf(nx) * (1.0f / HWF), 1e-6f);
        float nys = fmaxf(sqrtf(ny) * (1.0f / HWF), 1e-6f);
        cosv = (dot * (1.0f / (HWF * HWF))) / (nxs * nys);
    }
    s_red[tid] = cosv;
    __syncthreads();
#pragma unroll
    for (int stride = 64; stride > 0; stride >>= 1) {
        if (tid < stride) s_red[tid] += s_red[tid + stride];
        __syncthreads();
    }
    if (tid == 0) out[0] = s_red[0] * (1.0f / 96.0f);

    __syncthreads();
    for (int i = tid; i < 2 * PLANES * BINS; i += 128)
        ((unsigned int*)g_hist)[i] = 0u;
    if (tid == 0) g_ticket = 0u;
}

extern "C" void kernel_launch(void* const* d_in, const int* in_sizes, int n_in,
                              void* d_out, int out_size) {
    const float* x = (const float*)d_in[0];
    const float* y = (const float*)d_in[1];
    fused_hist_loss_kernel<<<NBLK, 128>>>(x, y, (float*)d_out);
}